// round 16
// baseline (speedup 1.0000x reference)
#include <cuda_runtime.h>
#include <cuda_fp16.h>
#include <cstdint>

#define NN 100000
#define NE 1600000
#define NCH ((NN + 255) / 256)
#define NT 8
#define TM 128
#define NTILES ((NN + TM - 1) / TM)   // 782
#define TSPLIT 391                     // tile split
#define NSPLIT (TSPLIT * TM)           // 50048 node split
#define NGROUPS (NN / NT)              // 12500 groups for trans3
#define GSPLIT (NSPLIT / NT)           // 6256

// ---------------- device scratch (no allocs allowed) ----------------
__device__ int    g_deg[NN];           // statically zero; re-zeroed by k_offsets each call
__device__ int    g_off[NN + 1];
__device__ int    g_cur[NN];
__device__ float  g_inv[NN];
__device__ int    g_csr[NE];
__device__ int    g_part[NCH];
__device__ float  g_h0[(size_t)NN * 64];
__device__ float  g_h1[(size_t)NN * 64];
__device__ __half g_t[(size_t)NN * 64];    // buffer A (layers 1, 3)
__device__ __half g_t2[(size_t)NN * 64];   // buffer B (layer 2)
__device__ float  g_s[(size_t)NN * 64];

// ---------------- f32x2 helpers ----------------
__device__ __forceinline__ unsigned long long pk2(float x, float y) {
    unsigned long long r;
    asm("mov.b64 %0,{%1,%2};" : "=l"(r) : "f"(x), "f"(y));
    return r;
}
__device__ __forceinline__ void upk2(unsigned long long v, float &x, float &y) {
    asm("mov.b64 {%0,%1},%2;" : "=f"(x), "=f"(y) : "l"(v));
}
__device__ __forceinline__ void fma2(unsigned long long &d, unsigned long long w, unsigned long long a) {
    asm("fma.rn.f32x2 %0,%1,%2,%0;" : "+l"(d) : "l"(w), "l"(a));
}

// ---------------- mma.sync helpers ----------------
__device__ __forceinline__ uint32_t smem_u32(const void* p) {
    uint32_t a;
    asm("{ .reg .u64 t; cvta.to.shared.u64 t, %1; cvt.u32.u64 %0, t; }" : "=r"(a) : "l"(p));
    return a;
}
#define SW128(x) ((x) ^ (((x) >> 3) & 0x70))
__device__ __forceinline__ void ldsm4(uint32_t &a0, uint32_t &a1, uint32_t &a2, uint32_t &a3, uint32_t addr) {
    asm volatile("ldmatrix.sync.aligned.m8n8.x4.shared.b16 {%0,%1,%2,%3}, [%4];"
                 : "=r"(a0), "=r"(a1), "=r"(a2), "=r"(a3) : "r"(addr));
}
__device__ __forceinline__ void ldsm2(uint32_t &b0, uint32_t &b1, uint32_t addr) {
    asm volatile("ldmatrix.sync.aligned.m8n8.x2.shared.b16 {%0,%1}, [%2];"
                 : "=r"(b0), "=r"(b1) : "r"(addr));
}
__device__ __forceinline__ void mma16816(float* c, const uint32_t* a, uint32_t b0, uint32_t b1) {
    asm volatile("mma.sync.aligned.m16n8k16.row.col.f32.f16.f16.f32 "
                 "{%0,%1,%2,%3}, {%4,%5,%6,%7}, {%8,%9}, {%0,%1,%2,%3};"
                 : "+f"(c[0]), "+f"(c[1]), "+f"(c[2]), "+f"(c[3])
                 : "r"(a[0]), "r"(a[1]), "r"(a[2]), "r"(a[3]), "r"(b0), "r"(b1));
}

// hi/lo fp16 split of a float4 -> two packed uint2 (two half2 each)
__device__ __forceinline__ void split4(const float4 &v, uint2 &hi, uint2 &lo) {
    __half2 h0 = __floats2half2_rn(v.x, v.y);
    __half2 h1 = __floats2half2_rn(v.z, v.w);
    float2 f0 = __half22float2(h0);
    float2 f1 = __half22float2(h1);
    __half2 l0 = __floats2half2_rn(v.x - f0.x, v.y - f0.y);
    __half2 l1 = __floats2half2_rn(v.z - f1.x, v.w - f1.y);
    hi = make_uint2(*(uint32_t*)&h0, *(uint32_t*)&h1);
    lo = make_uint2(*(uint32_t*)&l0, *(uint32_t*)&l1);
}

// ---------------- CSR construction ----------------
__global__ void k_count(const int* __restrict__ dst) {
    int i = blockIdx.x * blockDim.x + threadIdx.x;
    if (i < NE / 4) {
        int4 d = ((const int4*)dst)[i];
        atomicAdd(&g_deg[d.x], 1);
        atomicAdd(&g_deg[d.y], 1);
        atomicAdd(&g_deg[d.z], 1);
        atomicAdd(&g_deg[d.w], 1);
    }
}
__global__ void k_chunksum() {
    __shared__ int s[256];
    int t = threadIdx.x;
    int idx = blockIdx.x * 256 + t;
    s[t] = (idx < NN) ? g_deg[idx] : 0;
    __syncthreads();
    for (int o = 128; o > 0; o >>= 1) {
        if (t < o) s[t] += s[t + o];
        __syncthreads();
    }
    if (t == 0) g_part[blockIdx.x] = s[0];
}
__global__ void k_offsets() {
    __shared__ int red[256];
    __shared__ int s[256];
    __shared__ int sp;
    int t = threadIdx.x;
    int acc = 0;
    for (int i = t; i < blockIdx.x; i += 256) acc += g_part[i];
    red[t] = acc;
    __syncthreads();
    for (int o = 128; o > 0; o >>= 1) {
        if (t < o) red[t] += red[t + o];
        __syncthreads();
    }
    if (t == 0) sp = red[0];
    int idx = blockIdx.x * 256 + t;
    int d = (idx < NN) ? g_deg[idx] : 0;
    s[t] = d;
    __syncthreads();
    for (int o = 1; o < 256; o <<= 1) {
        int tmp = (t >= o) ? s[t - o] : 0;
        __syncthreads();
        s[t] += tmp;
        __syncthreads();
    }
    int off = sp + s[t] - d;
    if (idx < NN) {
        g_off[idx] = off;
        g_cur[idx] = off;
        int dd = d > 1 ? d : 1;
        g_inv[idx] = 1.0f / (float)dd;
        g_deg[idx] = 0;   // reset for next replay
    }
    if (idx == NN - 1) g_off[NN] = off + d;
}
__global__ void k_fill(const int* __restrict__ src, const int* __restrict__ dst) {
    int i = blockIdx.x * blockDim.x + threadIdx.x;
    if (i < NE / 4) {
        int4 d = ((const int4*)dst)[i];
        int4 s = ((const int4*)src)[i];
        g_csr[atomicAdd(&g_cur[d.x], 1)] = s.x;
        g_csr[atomicAdd(&g_cur[d.y], 1)] = s.y;
        g_csr[atomicAdd(&g_cur[d.z], 1)] = s.z;
        g_csr[atomicAdd(&g_cur[d.w], 1)] = s.w;
    }
}

// ---------------- k_wpre: h0 = x @ W_pre.T + b  (128 -> 64) on HMMA --------
__global__ __launch_bounds__(256, 2) void k_wpre(const float* __restrict__ x,
                                                 const float* __restrict__ W,
                                                 const float* __restrict__ b,
                                                 float* __restrict__ hout) {
    extern __shared__ char smraw[];
    uint32_t sbase = smem_u32(smraw);
    uint32_t ab = (sbase + 1023u) & ~1023u;
    char* pb = smraw + (ab - sbase);
    char* pA = pb;
    char* pB = pb + 65536;
    float* sBias = (float*)(pb + 81920);
    uint32_t aA = ab, aB = ab + 65536;

    int tid = threadIdx.x;
    int wid = tid >> 5, lane = tid & 31;
    int wm = wid & 3, wn = wid >> 2;

    for (int i = tid; i < 64 * 128; i += 256) {
        int n = i >> 7, k = i & 127;
        int buf = k >> 6;
        __half whi = __float2half_rn(W[i]);
        uint32_t off = SW128((uint32_t)(n * 128 + (k & 63) * 2));
        *(__half*)(pB + buf * 8192 + off) = whi;
    }
    if (tid < 64) sBias[tid] = b[tid];
    __syncthreads();

    for (int tile = blockIdx.x; tile < NTILES; tile += gridDim.x) {
        int v0 = tile * TM;
#pragma unroll
        for (int half = 0; half < 2; half++) {
            float4 vv[8];
#pragma unroll
            for (int i = 0; i < 8; i++) {
                int p = tid + (half * 8 + i) * 256;
                int r = p >> 5, c4 = p & 31;
                int v = v0 + r;
                vv[i] = (v < NN) ? *(const float4*)(x + (size_t)v * 128 + c4 * 4)
                                 : make_float4(0.f, 0.f, 0.f, 0.f);
            }
#pragma unroll
            for (int i = 0; i < 8; i++) {
                int p = tid + (half * 8 + i) * 256;
                int r = p >> 5, c4 = p & 31;
                int buf = c4 >> 4;
                int m = (2 * c4) & 31;
                uint2 hi, lo;
                split4(vv[i], hi, lo);
                uint32_t off = SW128((uint32_t)(r * 128 + m * 4));
                *(uint2*)(pA + buf * 16384 + off) = hi;
                *(uint2*)(pA + 32768 + buf * 16384 + off) = lo;
            }
        }
        __syncthreads();

        float acc[2][4][4];
#pragma unroll
        for (int mt = 0; mt < 2; mt++)
#pragma unroll
            for (int nt = 0; nt < 4; nt++)
#pragma unroll
                for (int i = 0; i < 4; i++) acc[mt][nt][i] = 0.f;

#pragma unroll
        for (int pass = 0; pass < 2; pass++) {
            uint32_t baseA = aA + ((pass == 1) ? 32768 : 0);
#pragma unroll
            for (int ks = 0; ks < 8; ks++) {
                int buf = ks >> 2, kk = ks & 3;
                uint32_t a[2][4];
#pragma unroll
                for (int mt = 0; mt < 2; mt++) {
                    uint32_t row = wm * 32 + mt * 16 + (lane & 15);
                    uint32_t off = SW128(row * 128 + kk * 32 + (lane >> 4) * 16);
                    ldsm4(a[mt][0], a[mt][1], a[mt][2], a[mt][3],
                          baseA + buf * 16384 + off);
                }
#pragma unroll
                for (int nt = 0; nt < 4; nt++) {
                    uint32_t n = wn * 32 + nt * 8 + (lane & 7);
                    uint32_t off = SW128(n * 128 + kk * 32 + ((lane >> 3) & 1) * 16);
                    uint32_t b0, b1;
                    ldsm2(b0, b1, aB + buf * 8192 + off);
                    mma16816(acc[0][nt], a[0], b0, b1);
                    mma16816(acc[1][nt], a[1], b0, b1);
                }
            }
        }

        int rbase = v0 + wm * 32;
#pragma unroll
        for (int mt = 0; mt < 2; mt++) {
            int r0 = rbase + mt * 16 + (lane >> 2);
#pragma unroll
            for (int nt = 0; nt < 4; nt++) {
                int c = wn * 32 + nt * 8 + 2 * (lane & 3);
                float bx = sBias[c], by = sBias[c + 1];
                if (r0 < NN)
                    *(float2*)(hout + (size_t)r0 * 64 + c) =
                        make_float2(acc[mt][nt][0] + bx, acc[mt][nt][1] + by);
                if (r0 + 8 < NN)
                    *(float2*)(hout + (size_t)(r0 + 8) * 64 + c) =
                        make_float2(acc[mt][nt][2] + bx, acc[mt][nt][3] + by);
            }
        }
        __syncthreads();
    }
}

// ---------------- k_wtrans: tile range [tileBeg, tileEnd) ------------------
__global__ __launch_bounds__(256, 2) void k_wtrans(const float* __restrict__ h,
                                                   const float* __restrict__ Wl,
                                                   const float* __restrict__ bl,
                                                   const float* __restrict__ Wr,
                                                   __half* __restrict__ tout,
                                                   float* __restrict__ sout,
                                                   int tileBeg, int tileEnd) {
    extern __shared__ char smraw[];
    uint32_t sbase = smem_u32(smraw);
    uint32_t ab = (sbase + 1023u) & ~1023u;
    char* pb = smraw + (ab - sbase);
    char* pA = pb;                    // hi 16K | lo 16K
    char* pB = pb + 32768;            // hi 16K
    float* sBias = (float*)(pb + 49152);
    uint32_t aA = ab, aB = ab + 32768;

    int tid = threadIdx.x;
    int wid = tid >> 5, lane = tid & 31;
    int wm = wid & 3, wn = wid >> 2;

    for (int i = tid; i < 128 * 64; i += 256) {
        int n = i >> 6, k = i & 63;
        float w = (n < 64) ? Wl[n * 64 + k] : Wr[(n - 64) * 64 + k];
        __half whi = __float2half_rn(w);
        uint32_t off = SW128((uint32_t)(n * 128 + k * 2));
        *(__half*)(pB + off) = whi;
    }
    if (tid < 64) sBias[tid] = bl[tid];
    __syncthreads();

    __half2* tout2 = (__half2*)tout;

    for (int tile = tileBeg + blockIdx.x; tile < tileEnd; tile += gridDim.x) {
        int v0 = tile * TM;
        {
            float4 vv[8];
#pragma unroll
            for (int i = 0; i < 8; i++) {
                int p = tid + i * 256;
                int r = p >> 4, c4 = p & 15;
                int v = v0 + r;
                vv[i] = (v < NN) ? *(const float4*)(h + (size_t)v * 64 + c4 * 4)
                                 : make_float4(0.f, 0.f, 0.f, 0.f);
            }
#pragma unroll
            for (int i = 0; i < 8; i++) {
                int p = tid + i * 256;
                int r = p >> 4, c4 = p & 15;
                uint2 hi, lo;
                split4(vv[i], hi, lo);
                uint32_t off = SW128((uint32_t)(r * 128 + c4 * 8));
                *(uint2*)(pA + off) = hi;
                *(uint2*)(pA + 16384 + off) = lo;
            }
        }
        __syncthreads();

        float acc[2][8][4];
#pragma unroll
        for (int mt = 0; mt < 2; mt++)
#pragma unroll
            for (int nt = 0; nt < 8; nt++)
#pragma unroll
                for (int i = 0; i < 4; i++) acc[mt][nt][i] = 0.f;

#pragma unroll
        for (int pass = 0; pass < 2; pass++) {
            uint32_t baseA = aA + ((pass == 1) ? 16384 : 0);
#pragma unroll
            for (int ks = 0; ks < 4; ks++) {
                uint32_t a[2][4];
#pragma unroll
                for (int mt = 0; mt < 2; mt++) {
                    uint32_t row = wm * 32 + mt * 16 + (lane & 15);
                    uint32_t off = SW128(row * 128 + ks * 32 + (lane >> 4) * 16);
                    ldsm4(a[mt][0], a[mt][1], a[mt][2], a[mt][3], baseA + off);
                }
#pragma unroll
                for (int nt = 0; nt < 8; nt++) {
                    uint32_t n = wn * 64 + nt * 8 + (lane & 7);
                    uint32_t off = SW128(n * 128 + ks * 32 + ((lane >> 3) & 1) * 16);
                    uint32_t b0, b1;
                    ldsm2(b0, b1, aB + off);
                    mma16816(acc[0][nt], a[0], b0, b1);
                    mma16816(acc[1][nt], a[1], b0, b1);
                }
            }
        }

        int rbase = v0 + wm * 32;
        if (wn == 0) {
#pragma unroll
            for (int mt = 0; mt < 2; mt++) {
                int r0 = rbase + mt * 16 + (lane >> 2);
#pragma unroll
                for (int nt = 0; nt < 8; nt++) {
                    int c = nt * 8 + 2 * (lane & 3);
                    if (r0 < NN)
                        tout2[(size_t)r0 * 32 + (c >> 1)] =
                            __floats2half2_rn(acc[mt][nt][0], acc[mt][nt][1]);
                    if (r0 + 8 < NN)
                        tout2[(size_t)(r0 + 8) * 32 + (c >> 1)] =
                            __floats2half2_rn(acc[mt][nt][2], acc[mt][nt][3]);
                }
            }
        } else {
#pragma unroll
            for (int mt = 0; mt < 2; mt++) {
                int r0 = rbase + mt * 16 + (lane >> 2);
#pragma unroll
                for (int nt = 0; nt < 8; nt++) {
                    int c = nt * 8 + 2 * (lane & 3);
                    float bx = sBias[c], by = sBias[c + 1];
                    if (r0 < NN)
                        *(float2*)(sout + (size_t)r0 * 64 + c) =
                            make_float2(acc[mt][nt][0] + bx, acc[mt][nt][1] + by);
                    if (r0 + 8 < NN)
                        *(float2*)(sout + (size_t)(r0 + 8) * 64 + c) =
                            make_float2(acc[mt][nt][2] + bx, acc[mt][nt][3] + by);
                }
            }
        }
        __syncthreads();
    }
}

// ---------------- k_aggrelu: node range [vBeg, vEnd) ----------
__global__ __launch_bounds__(256, 8) void k_aggrelu(const __half* __restrict__ t,
                                                    const float* __restrict__ s,
                                                    float* __restrict__ hout,
                                                    int vBeg, int vEnd) {
    const __half2* t2 = (const __half2*)t;
    int warp = threadIdx.x >> 5, lane = threadIdx.x & 31;
    int gw = blockIdx.x * 8 + warp;
    int nw = gridDim.x * 8;
    for (int v = vBeg + gw; v < vEnd; v += nw) {
        int beg = g_off[v], end = g_off[v + 1];
        float ax = 0.f, ay = 0.f;
        for (int base = beg; base < end; base += 32) {
            int rem = end - base;
            int m = rem < 32 ? rem : 32;
            int sv = (lane < m) ? g_csr[base + lane] : 0;
            int q = 0;
            for (; q + 8 <= m; q += 8) {
                int u[8];
#pragma unroll
                for (int i = 0; i < 8; i++) u[i] = __shfl_sync(0xffffffffu, sv, q + i);
                __half2 hv[8];
#pragma unroll
                for (int i = 0; i < 8; i++) hv[i] = t2[(size_t)u[i] * 32 + lane];
#pragma unroll
                for (int i = 0; i < 8; i++) {
                    float2 f = __half22float2(hv[i]);
                    ax += f.x;
                    ay += f.y;
                }
            }
            for (; q < m; q++) {
                int u = __shfl_sync(0xffffffffu, sv, q);
                float2 f = __half22float2(t2[(size_t)u * 32 + lane]);
                ax += f.x;
                ay += f.y;
            }
        }
        float idg = g_inv[v];
        float2 sv2 = *(const float2*)(s + (size_t)v * 64 + lane * 2);
        float ox = fmaxf(ax * idg + sv2.x, 0.f);
        float oy = fmaxf(ay * idg + sv2.y, 0.f);
        *(float2*)(hout + (size_t)v * 64 + lane * 2) = make_float2(ox, oy);
    }
}

// ---------------- k_trans3: group range [gBeg, gEnd) ----------------
__global__ __launch_bounds__(256) void k_trans3(const float* __restrict__ h,
                                                const float* __restrict__ Wl,
                                                const float* __restrict__ bl,
                                                const float* __restrict__ Wr,
                                                __half* __restrict__ tout,
                                                float* __restrict__ sout,
                                                int gBeg, int gEnd) {
    extern __shared__ float sm[];
    float* sWl = sm;
    float* sWr = sm + 2048;
    float* sX  = sm + 4096;
    for (int i = threadIdx.x; i < 2048; i += blockDim.x) {
        int j = i >> 6, k = i & 63;
        int idx = (k >> 1) * 64 + (j << 1) + (k & 1);
        sWl[idx] = Wl[i];
        sWr[idx] = Wr[i];
    }
    __syncthreads();
    const unsigned long long* sWl2 = (const unsigned long long*)sWl;
    const unsigned long long* sWr2 = (const unsigned long long*)sWr;
    int warp = threadIdx.x >> 5, lane = threadIdx.x & 31;
    float bj = bl[lane];
    float* sXw = sX + warp * (NT * 64);
    int gwarp = blockIdx.x * 8 + warp;
    int nwarp = gridDim.x * 8;
    __half2* tout2 = (__half2*)tout;
    for (int g = gBeg + gwarp; g < gEnd; g += nwarp) {
        int v0 = g * NT;
#pragma unroll
        for (int n = 0; n < NT; n++) {
            float2 hv = *(const float2*)(h + (size_t)(v0 + n) * 64 + lane * 2);
            *(float2*)(sXw + n * 64 + lane * 2) = hv;
        }
        __syncwarp();
        unsigned long long at[NT], as[NT];
#pragma unroll
        for (int n = 0; n < NT; n++) {
            at[n] = pk2(0.f, 0.f);
            as[n] = pk2(0.f, 0.f);
        }
        for (int p = 0; p < 32; p += 2) {
            unsigned long long wl0 = sWl2[(p + 0) * 32 + lane];
            unsigned long long wl1 = sWl2[(p + 1) * 32 + lane];
            unsigned long long wr0 = sWr2[(p + 0) * 32 + lane];
            unsigned long long wr1 = sWr2[(p + 1) * 32 + lane];
#pragma unroll
            for (int n = 0; n < NT; n++) {
                float4 a = *(const float4*)(sXw + n * 64 + p * 2);
                unsigned long long a01 = pk2(a.x, a.y);
                unsigned long long a23 = pk2(a.z, a.w);
                fma2(at[n], wl0, a01);
                fma2(at[n], wl1, a23);
                fma2(as[n], wr0, a01);
                fma2(as[n], wr1, a23);
            }
        }
#pragma unroll
        for (int n = 0; n < NT; n++) {
            float tx, ty, sx, sy;
            upk2(at[n], tx, ty);
            upk2(as[n], sx, sy);
            float tj = tx + ty;
            float sj = sx + sy + bj;
            sout[(size_t)(v0 + n) * 32 + lane] = sj;
            float thi = __shfl_down_sync(0xffffffffu, tj, 1);
            if (!(lane & 1))
                tout2[(size_t)(v0 + n) * 16 + (lane >> 1)] = __floats2half2_rn(tj, thi);
        }
        __syncwarp();
    }
}

// ---------------- k_aggnorm ----------------
__global__ __launch_bounds__(256, 8) void k_aggnorm(const __half* __restrict__ t,
                                                    const float* __restrict__ s,
                                                    float* __restrict__ out) {
    const __half2* t2 = (const __half2*)t;
    int warp = threadIdx.x >> 5, lane = threadIdx.x & 31;
    int m = lane & 15;
    int hi = lane >> 4;
    int gw = blockIdx.x * 8 + warp;
    int nw = gridDim.x * 8;
    for (int v = gw; v < NN; v += nw) {
        int beg = g_off[v], end = g_off[v + 1];
        float ax = 0.f, ay = 0.f;
        for (int base = beg; base < end; base += 32) {
            int rem = end - base;
            int mm = rem < 32 ? rem : 32;
            int sv = (lane < mm) ? g_csr[base + lane] : 0;
            int q = 0;
            for (; q + 8 <= mm; q += 8) {
                int u[4];
#pragma unroll
                for (int i = 0; i < 4; i++)
                    u[i] = __shfl_sync(0xffffffffu, sv, q + 2 * i + hi);
                __half2 hv[4];
#pragma unroll
                for (int i = 0; i < 4; i++) hv[i] = t2[(size_t)u[i] * 16 + m];
#pragma unroll
                for (int i = 0; i < 4; i++) {
                    float2 f = __half22float2(hv[i]);
                    ax += f.x;
                    ay += f.y;
                }
            }
            for (; q + 2 <= mm; q += 2) {
                int u = __shfl_sync(0xffffffffu, sv, q + hi);
                float2 f = __half22float2(t2[(size_t)u * 16 + m]);
                ax += f.x;
                ay += f.y;
            }
            if (q < mm) {
                int u = __shfl_sync(0xffffffffu, sv, q);
                if (!hi) {
                    float2 f = __half22float2(t2[(size_t)u * 16 + m]);
                    ax += f.x;
                    ay += f.y;
                }
            }
        }
        ax += __shfl_xor_sync(0xffffffffu, ax, 16);
        ay += __shfl_xor_sync(0xffffffffu, ay, 16);
        float idg = g_inv[v];
        float2 sv2 = *(const float2*)(s + (size_t)v * 32 + m * 2);
        float ox = ax * idg + sv2.x;
        float oy = ay * idg + sv2.y;
        float ss = ox * ox + oy * oy;
#pragma unroll
        for (int off = 8; off; off >>= 1)
            ss += __shfl_xor_sync(0xffffffffu, ss, off);
        float nrm = fmaxf(sqrtf(ss), 1e-12f);
        if (!hi)
            *(float2*)(out + (size_t)v * 32 + m * 2) = make_float2(ox / nrm, oy / nrm);
    }
}

// ---------------- launch ----------------
extern "C" void kernel_launch(void* const* d_in, const int* in_sizes, int n_in,
                              void* d_out, int out_size) {
    const float* x     = (const float*)d_in[0];
    const int*   ei    = (const int*)d_in[1];
    const float* W_pre = (const float*)d_in[2];
    const float* b_pre = (const float*)d_in[3];
    const float* Wl1 = (const float*)d_in[4];
    const float* bl1 = (const float*)d_in[5];
    const float* Wr1 = (const float*)d_in[6];
    const float* Wl2 = (const float*)d_in[7];
    const float* bl2 = (const float*)d_in[8];
    const float* Wr2 = (const float*)d_in[9];
    const float* Wl3 = (const float*)d_in[10];
    const float* bl3 = (const float*)d_in[11];
    const float* Wr3 = (const float*)d_in[12];
    float* out = (float*)d_out;
    const int* src = ei;
    const int* dst = ei + NE;

    float *ph0, *ph1, *ps;
    __half *ptA, *ptB;
    cudaGetSymbolAddress((void**)&ph0, g_h0);
    cudaGetSymbolAddress((void**)&ph1, g_h1);
    cudaGetSymbolAddress((void**)&ptA, g_t);
    cudaGetSymbolAddress((void**)&ptB, g_t2);
    cudaGetSymbolAddress((void**)&ps, g_s);

    const int GRIDA = 1184;
    const int GRIDW = 592;
    const int PSMEM = 83200;
    const int TSMEM = 50432;

    cudaFuncSetAttribute(k_wpre, cudaFuncAttributeMaxDynamicSharedMemorySize, PSMEM);
    cudaFuncSetAttribute(k_wtrans, cudaFuncAttributeMaxDynamicSharedMemorySize, TSMEM);

    cudaStream_t s2;
    cudaStreamCreateWithFlags(&s2, cudaStreamNonBlocking);
    cudaEvent_t eFork, eJoin, eA1a, eW2a, eA2a, eT3a;
    cudaEventCreateWithFlags(&eFork, cudaEventDisableTiming);
    cudaEventCreateWithFlags(&eJoin, cudaEventDisableTiming);
    cudaEventCreateWithFlags(&eA1a, cudaEventDisableTiming);
    cudaEventCreateWithFlags(&eW2a, cudaEventDisableTiming);
    cudaEventCreateWithFlags(&eA2a, cudaEventDisableTiming);
    cudaEventCreateWithFlags(&eT3a, cudaEventDisableTiming);

    // ---- fork: CSR on s2, dense prologue on main ----
    cudaEventRecord(eFork, 0);
    cudaStreamWaitEvent(s2, eFork, 0);
    k_count<<<(NE / 4 + 255) / 256, 256, 0, s2>>>(dst);
    k_chunksum<<<NCH, 256, 0, s2>>>();
    k_offsets<<<NCH, 256, 0, s2>>>();
    k_fill<<<(NE / 4 + 255) / 256, 256, 0, s2>>>(src, dst);
    cudaEventRecord(eJoin, s2);

    k_wpre<<<296, 256, PSMEM>>>(x, W_pre, b_pre, ph0);
    k_wtrans<<<GRIDW, 256, TSMEM>>>(ph0, Wl1, bl1, Wr1, ptA, ps, 0, NTILES);   // layer1 -> tA
    cudaStreamWaitEvent(0, eJoin, 0);

    // ---- layer1 agg (reads tA); wtrans2 first half (writes tB) overlapped --
    k_aggrelu<<<GRIDA, 256>>>(ptA, ps, ph1, 0, NSPLIT);
    cudaEventRecord(eA1a, 0);
    cudaStreamWaitEvent(s2, eA1a, 0);
    k_wtrans<<<GRIDW, 256, TSMEM, s2>>>(ph1, Wl2, bl2, Wr2, ptB, ps, 0, TSPLIT);
    cudaEventRecord(eW2a, s2);
    k_aggrelu<<<GRIDA, 256>>>(ptA, ps, ph1, NSPLIT, NN);
    k_wtrans<<<GRIDW, 256, TSMEM>>>(ph1, Wl2, bl2, Wr2, ptB, ps, TSPLIT, NTILES);
    cudaStreamWaitEvent(0, eW2a, 0);

    // ---- layer2 agg (reads tB); trans3 first half (writes tA) overlapped ---
    k_aggrelu<<<GRIDA, 256>>>(ptB, ps, ph0, 0, NSPLIT);
    cudaEventRecord(eA2a, 0);
    cudaStreamWaitEvent(s2, eA2a, 0);
    k_trans3<<<GRIDW, 256, 32768, s2>>>(ph0, Wl3, bl3, Wr3, ptA, ps, 0, GSPLIT);
    cudaEventRecord(eT3a, s2);
    k_aggrelu<<<GRIDA, 256>>>(ptB, ps, ph0, NSPLIT, NN);
    k_trans3<<<GRIDW, 256, 32768>>>(ph0, Wl3, bl3, Wr3, ptA, ps, GSPLIT, NGROUPS);
    cudaStreamWaitEvent(0, eT3a, 0);

    // ---- final aggregate + normalize (reads tA 32-dim + s 32-dim) ----
    k_aggnorm<<<GRIDA, 256>>>(ptA, ps, out);
}

// round 17
// speedup vs baseline: 1.0647x; 1.0647x over previous
#include <cuda_runtime.h>
#include <cuda_fp16.h>
#include <cstdint>

#define NN 100000
#define NE 1600000
#define NCH ((NN + 255) / 256)
#define NT 8
#define TM 128
#define NTILES ((NN + TM - 1) / TM)   // 782

// ---------------- device scratch (no allocs allowed) ----------------
__device__ int    g_deg[NN];           // statically zero; re-zeroed by k_offsets each call
__device__ int    g_off[NN + 1];
__device__ int    g_cur[NN];
__device__ float  g_inv[NN];
__device__ int    g_csr[NE];
__device__ int    g_part[NCH];
__device__ float  g_h0[(size_t)NN * 64];
__device__ float  g_h1[(size_t)NN * 64];
__device__ __half g_t[(size_t)NN * 64];
__device__ __half g_s[(size_t)NN * 64];   // self term, fp16 (bias added in fp32 pre-round)

// ---------------- f32x2 helpers ----------------
__device__ __forceinline__ unsigned long long pk2(float x, float y) {
    unsigned long long r;
    asm("mov.b64 %0,{%1,%2};" : "=l"(r) : "f"(x), "f"(y));
    return r;
}
__device__ __forceinline__ void upk2(unsigned long long v, float &x, float &y) {
    asm("mov.b64 {%0,%1},%2;" : "=f"(x), "=f"(y) : "l"(v));
}
__device__ __forceinline__ void fma2(unsigned long long &d, unsigned long long w, unsigned long long a) {
    asm("fma.rn.f32x2 %0,%1,%2,%0;" : "+l"(d) : "l"(w), "l"(a));
}

// ---------------- mma.sync helpers ----------------
__device__ __forceinline__ uint32_t smem_u32(const void* p) {
    uint32_t a;
    asm("{ .reg .u64 t; cvta.to.shared.u64 t, %1; cvt.u32.u64 %0, t; }" : "=r"(a) : "l"(p));
    return a;
}
#define SW128(x) ((x) ^ (((x) >> 3) & 0x70))
__device__ __forceinline__ void ldsm4(uint32_t &a0, uint32_t &a1, uint32_t &a2, uint32_t &a3, uint32_t addr) {
    asm volatile("ldmatrix.sync.aligned.m8n8.x4.shared.b16 {%0,%1,%2,%3}, [%4];"
                 : "=r"(a0), "=r"(a1), "=r"(a2), "=r"(a3) : "r"(addr));
}
__device__ __forceinline__ void ldsm2(uint32_t &b0, uint32_t &b1, uint32_t addr) {
    asm volatile("ldmatrix.sync.aligned.m8n8.x2.shared.b16 {%0,%1}, [%2];"
                 : "=r"(b0), "=r"(b1) : "r"(addr));
}
__device__ __forceinline__ void mma16816(float* c, const uint32_t* a, uint32_t b0, uint32_t b1) {
    asm volatile("mma.sync.aligned.m16n8k16.row.col.f32.f16.f16.f32 "
                 "{%0,%1,%2,%3}, {%4,%5,%6,%7}, {%8,%9}, {%0,%1,%2,%3};"
                 : "+f"(c[0]), "+f"(c[1]), "+f"(c[2]), "+f"(c[3])
                 : "r"(a[0]), "r"(a[1]), "r"(a[2]), "r"(a[3]), "r"(b0), "r"(b1));
}

// hi/lo fp16 split of a float4 -> two packed uint2 (two half2 each)
__device__ __forceinline__ void split4(const float4 &v, uint2 &hi, uint2 &lo) {
    __half2 h0 = __floats2half2_rn(v.x, v.y);
    __half2 h1 = __floats2half2_rn(v.z, v.w);
    float2 f0 = __half22float2(h0);
    float2 f1 = __half22float2(h1);
    __half2 l0 = __floats2half2_rn(v.x - f0.x, v.y - f0.y);
    __half2 l1 = __floats2half2_rn(v.z - f1.x, v.w - f1.y);
    hi = make_uint2(*(uint32_t*)&h0, *(uint32_t*)&h1);
    lo = make_uint2(*(uint32_t*)&l0, *(uint32_t*)&l1);
}

// ---------------- CSR construction ----------------
__global__ void k_count(const int* __restrict__ dst) {
    int i = blockIdx.x * blockDim.x + threadIdx.x;
    if (i < NE / 4) {
        int4 d = ((const int4*)dst)[i];
        atomicAdd(&g_deg[d.x], 1);
        atomicAdd(&g_deg[d.y], 1);
        atomicAdd(&g_deg[d.z], 1);
        atomicAdd(&g_deg[d.w], 1);
    }
}
__global__ void k_chunksum() {
    __shared__ int s[256];
    int t = threadIdx.x;
    int idx = blockIdx.x * 256 + t;
    s[t] = (idx < NN) ? g_deg[idx] : 0;
    __syncthreads();
    for (int o = 128; o > 0; o >>= 1) {
        if (t < o) s[t] += s[t + o];
        __syncthreads();
    }
    if (t == 0) g_part[blockIdx.x] = s[0];
}
__global__ void k_offsets() {
    __shared__ int red[256];
    __shared__ int s[256];
    __shared__ int sp;
    int t = threadIdx.x;
    int acc = 0;
    for (int i = t; i < blockIdx.x; i += 256) acc += g_part[i];
    red[t] = acc;
    __syncthreads();
    for (int o = 128; o > 0; o >>= 1) {
        if (t < o) red[t] += red[t + o];
        __syncthreads();
    }
    if (t == 0) sp = red[0];
    int idx = blockIdx.x * 256 + t;
    int d = (idx < NN) ? g_deg[idx] : 0;
    s[t] = d;
    __syncthreads();
    for (int o = 1; o < 256; o <<= 1) {
        int tmp = (t >= o) ? s[t - o] : 0;
        __syncthreads();
        s[t] += tmp;
        __syncthreads();
    }
    int off = sp + s[t] - d;
    if (idx < NN) {
        g_off[idx] = off;
        g_cur[idx] = off;
        int dd = d > 1 ? d : 1;
        g_inv[idx] = 1.0f / (float)dd;
        g_deg[idx] = 0;   // reset for next replay
    }
    if (idx == NN - 1) g_off[NN] = off + d;
}
__global__ void k_fill(const int* __restrict__ src, const int* __restrict__ dst) {
    int i = blockIdx.x * blockDim.x + threadIdx.x;
    if (i < NE / 4) {
        int4 d = ((const int4*)dst)[i];
        int4 s = ((const int4*)src)[i];
        g_csr[atomicAdd(&g_cur[d.x], 1)] = s.x;
        g_csr[atomicAdd(&g_cur[d.y], 1)] = s.y;
        g_csr[atomicAdd(&g_cur[d.z], 1)] = s.z;
        g_csr[atomicAdd(&g_cur[d.w], 1)] = s.w;
    }
}

// ---------------- k_wpre: h0 = x @ W_pre.T + b  (128 -> 64) on HMMA --------
__global__ __launch_bounds__(256, 2) void k_wpre(const float* __restrict__ x,
                                                 const float* __restrict__ W,
                                                 const float* __restrict__ b,
                                                 float* __restrict__ hout) {
    extern __shared__ char smraw[];
    uint32_t sbase = smem_u32(smraw);
    uint32_t ab = (sbase + 1023u) & ~1023u;
    char* pb = smraw + (ab - sbase);
    char* pA = pb;
    char* pB = pb + 65536;
    float* sBias = (float*)(pb + 81920);
    uint32_t aA = ab, aB = ab + 65536;

    int tid = threadIdx.x;
    int wid = tid >> 5, lane = tid & 31;
    int wm = wid & 3, wn = wid >> 2;

    for (int i = tid; i < 64 * 128; i += 256) {
        int n = i >> 7, k = i & 127;
        int buf = k >> 6;
        __half whi = __float2half_rn(W[i]);
        uint32_t off = SW128((uint32_t)(n * 128 + (k & 63) * 2));
        *(__half*)(pB + buf * 8192 + off) = whi;
    }
    if (tid < 64) sBias[tid] = b[tid];
    __syncthreads();

    for (int tile = blockIdx.x; tile < NTILES; tile += gridDim.x) {
        int v0 = tile * TM;
#pragma unroll
        for (int half = 0; half < 2; half++) {
            float4 vv[8];
#pragma unroll
            for (int i = 0; i < 8; i++) {
                int p = tid + (half * 8 + i) * 256;
                int r = p >> 5, c4 = p & 31;
                int v = v0 + r;
                vv[i] = (v < NN) ? *(const float4*)(x + (size_t)v * 128 + c4 * 4)
                                 : make_float4(0.f, 0.f, 0.f, 0.f);
            }
#pragma unroll
            for (int i = 0; i < 8; i++) {
                int p = tid + (half * 8 + i) * 256;
                int r = p >> 5, c4 = p & 31;
                int buf = c4 >> 4;
                int m = (2 * c4) & 31;
                uint2 hi, lo;
                split4(vv[i], hi, lo);
                uint32_t off = SW128((uint32_t)(r * 128 + m * 4));
                *(uint2*)(pA + buf * 16384 + off) = hi;
                *(uint2*)(pA + 32768 + buf * 16384 + off) = lo;
            }
        }
        __syncthreads();

        float acc[2][4][4];
#pragma unroll
        for (int mt = 0; mt < 2; mt++)
#pragma unroll
            for (int nt = 0; nt < 4; nt++)
#pragma unroll
                for (int i = 0; i < 4; i++) acc[mt][nt][i] = 0.f;

#pragma unroll
        for (int pass = 0; pass < 2; pass++) {
            uint32_t baseA = aA + ((pass == 1) ? 32768 : 0);
#pragma unroll
            for (int ks = 0; ks < 8; ks++) {
                int buf = ks >> 2, kk = ks & 3;
                uint32_t a[2][4];
#pragma unroll
                for (int mt = 0; mt < 2; mt++) {
                    uint32_t row = wm * 32 + mt * 16 + (lane & 15);
                    uint32_t off = SW128(row * 128 + kk * 32 + (lane >> 4) * 16);
                    ldsm4(a[mt][0], a[mt][1], a[mt][2], a[mt][3],
                          baseA + buf * 16384 + off);
                }
#pragma unroll
                for (int nt = 0; nt < 4; nt++) {
                    uint32_t n = wn * 32 + nt * 8 + (lane & 7);
                    uint32_t off = SW128(n * 128 + kk * 32 + ((lane >> 3) & 1) * 16);
                    uint32_t b0, b1;
                    ldsm2(b0, b1, aB + buf * 8192 + off);
                    mma16816(acc[0][nt], a[0], b0, b1);
                    mma16816(acc[1][nt], a[1], b0, b1);
                }
            }
        }

        int rbase = v0 + wm * 32;
#pragma unroll
        for (int mt = 0; mt < 2; mt++) {
            int r0 = rbase + mt * 16 + (lane >> 2);
#pragma unroll
            for (int nt = 0; nt < 4; nt++) {
                int c = wn * 32 + nt * 8 + 2 * (lane & 3);
                float bx = sBias[c], by = sBias[c + 1];
                if (r0 < NN)
                    *(float2*)(hout + (size_t)r0 * 64 + c) =
                        make_float2(acc[mt][nt][0] + bx, acc[mt][nt][1] + by);
                if (r0 + 8 < NN)
                    *(float2*)(hout + (size_t)(r0 + 8) * 64 + c) =
                        make_float2(acc[mt][nt][2] + bx, acc[mt][nt][3] + by);
            }
        }
        __syncthreads();
    }
}

// ---------------- k_wtrans: D[128x128] = h[128x64] @ [Wl;Wr]^T on HMMA -----
// outputs: t (cols 0..63, fp16) and s (cols 64..127, fp16 with fp32 bias add)
__global__ __launch_bounds__(256, 2) void k_wtrans(const float* __restrict__ h,
                                                   const float* __restrict__ Wl,
                                                   const float* __restrict__ bl,
                                                   const float* __restrict__ Wr,
                                                   __half* __restrict__ tout,
                                                   __half* __restrict__ sout) {
    extern __shared__ char smraw[];
    uint32_t sbase = smem_u32(smraw);
    uint32_t ab = (sbase + 1023u) & ~1023u;
    char* pb = smraw + (ab - sbase);
    char* pA = pb;                    // hi 16K | lo 16K
    char* pB = pb + 32768;            // hi 16K
    float* sBias = (float*)(pb + 49152);
    uint32_t aA = ab, aB = ab + 32768;

    int tid = threadIdx.x;
    int wid = tid >> 5, lane = tid & 31;
    int wm = wid & 3, wn = wid >> 2;

    for (int i = tid; i < 128 * 64; i += 256) {
        int n = i >> 6, k = i & 63;
        float w = (n < 64) ? Wl[n * 64 + k] : Wr[(n - 64) * 64 + k];
        __half whi = __float2half_rn(w);
        uint32_t off = SW128((uint32_t)(n * 128 + k * 2));
        *(__half*)(pB + off) = whi;
    }
    if (tid < 64) sBias[tid] = bl[tid];
    __syncthreads();

    __half2* tout2 = (__half2*)tout;
    __half2* sout2 = (__half2*)sout;

    for (int tile = blockIdx.x; tile < NTILES; tile += gridDim.x) {
        int v0 = tile * TM;
        {
            float4 vv[8];
#pragma unroll
            for (int i = 0; i < 8; i++) {
                int p = tid + i * 256;
                int r = p >> 4, c4 = p & 15;
                int v = v0 + r;
                vv[i] = (v < NN) ? *(const float4*)(h + (size_t)v * 64 + c4 * 4)
                                 : make_float4(0.f, 0.f, 0.f, 0.f);
            }
#pragma unroll
            for (int i = 0; i < 8; i++) {
                int p = tid + i * 256;
                int r = p >> 4, c4 = p & 15;
                uint2 hi, lo;
                split4(vv[i], hi, lo);
                uint32_t off = SW128((uint32_t)(r * 128 + c4 * 8));
                *(uint2*)(pA + off) = hi;
                *(uint2*)(pA + 16384 + off) = lo;
            }
        }
        __syncthreads();

        float acc[2][8][4];
#pragma unroll
        for (int mt = 0; mt < 2; mt++)
#pragma unroll
            for (int nt = 0; nt < 8; nt++)
#pragma unroll
                for (int i = 0; i < 4; i++) acc[mt][nt][i] = 0.f;

#pragma unroll
        for (int pass = 0; pass < 2; pass++) {
            uint32_t baseA = aA + ((pass == 1) ? 16384 : 0);
#pragma unroll
            for (int ks = 0; ks < 4; ks++) {
                uint32_t a[2][4];
#pragma unroll
                for (int mt = 0; mt < 2; mt++) {
                    uint32_t row = wm * 32 + mt * 16 + (lane & 15);
                    uint32_t off = SW128(row * 128 + ks * 32 + (lane >> 4) * 16);
                    ldsm4(a[mt][0], a[mt][1], a[mt][2], a[mt][3], baseA + off);
                }
#pragma unroll
                for (int nt = 0; nt < 8; nt++) {
                    uint32_t n = wn * 64 + nt * 8 + (lane & 7);
                    uint32_t off = SW128(n * 128 + ks * 32 + ((lane >> 3) & 1) * 16);
                    uint32_t b0, b1;
                    ldsm2(b0, b1, aB + off);
                    mma16816(acc[0][nt], a[0], b0, b1);
                    mma16816(acc[1][nt], a[1], b0, b1);
                }
            }
        }

        int rbase = v0 + wm * 32;
        if (wn == 0) {
#pragma unroll
            for (int mt = 0; mt < 2; mt++) {
                int r0 = rbase + mt * 16 + (lane >> 2);
#pragma unroll
                for (int nt = 0; nt < 8; nt++) {
                    int c = nt * 8 + 2 * (lane & 3);
                    if (r0 < NN)
                        tout2[(size_t)r0 * 32 + (c >> 1)] =
                            __floats2half2_rn(acc[mt][nt][0], acc[mt][nt][1]);
                    if (r0 + 8 < NN)
                        tout2[(size_t)(r0 + 8) * 32 + (c >> 1)] =
                            __floats2half2_rn(acc[mt][nt][2], acc[mt][nt][3]);
                }
            }
        } else {
#pragma unroll
            for (int mt = 0; mt < 2; mt++) {
                int r0 = rbase + mt * 16 + (lane >> 2);
#pragma unroll
                for (int nt = 0; nt < 8; nt++) {
                    int c = nt * 8 + 2 * (lane & 3);
                    float bx = sBias[c], by = sBias[c + 1];
                    if (r0 < NN)
                        sout2[(size_t)r0 * 32 + (c >> 1)] =
                            __floats2half2_rn(acc[mt][nt][0] + bx, acc[mt][nt][1] + by);
                    if (r0 + 8 < NN)
                        sout2[(size_t)(r0 + 8) * 32 + (c >> 1)] =
                            __floats2half2_rn(acc[mt][nt][2] + bx, acc[mt][nt][3] + by);
                }
            }
        }
        __syncthreads();
    }
}

// ---------------- k_aggrelu: warp per node, 8-deep gather ----------
__global__ __launch_bounds__(256, 8) void k_aggrelu(const __half* __restrict__ t,
                                                    const __half* __restrict__ s,
                                                    float* __restrict__ hout) {
    const __half2* t2 = (const __half2*)t;
    const __half2* s2 = (const __half2*)s;
    int warp = threadIdx.x >> 5, lane = threadIdx.x & 31;
    int gw = blockIdx.x * 8 + warp;
    int nw = gridDim.x * 8;
    for (int v = gw; v < NN; v += nw) {
        int beg = g_off[v], end = g_off[v + 1];
        float ax = 0.f, ay = 0.f;
        for (int base = beg; base < end; base += 32) {
            int rem = end - base;
            int m = rem < 32 ? rem : 32;
            int sv = (lane < m) ? g_csr[base + lane] : 0;
            int q = 0;
            for (; q + 8 <= m; q += 8) {
                int u[8];
#pragma unroll
                for (int i = 0; i < 8; i++) u[i] = __shfl_sync(0xffffffffu, sv, q + i);
                __half2 hv[8];
#pragma unroll
                for (int i = 0; i < 8; i++) hv[i] = t2[(size_t)u[i] * 32 + lane];
#pragma unroll
                for (int i = 0; i < 8; i++) {
                    float2 f = __half22float2(hv[i]);
                    ax += f.x;
                    ay += f.y;
                }
            }
            for (; q < m; q++) {
                int u = __shfl_sync(0xffffffffu, sv, q);
                float2 f = __half22float2(t2[(size_t)u * 32 + lane]);
                ax += f.x;
                ay += f.y;
            }
        }
        float idg = g_inv[v];
        float2 sv2 = __half22float2(s2[(size_t)v * 32 + lane]);
        float ox = fmaxf(ax * idg + sv2.x, 0.f);
        float oy = fmaxf(ay * idg + sv2.y, 0.f);
        *(float2*)(hout + (size_t)v * 64 + lane * 2) = make_float2(ox, oy);
    }
}

// ---------------- k_trans3: (64 -> 32) scalar; t,s fp16 ----------------
__global__ __launch_bounds__(256) void k_trans3(const float* __restrict__ h,
                                                const float* __restrict__ Wl,
                                                const float* __restrict__ bl,
                                                const float* __restrict__ Wr,
                                                __half* __restrict__ tout,
                                                __half* __restrict__ sout) {
    extern __shared__ float sm[];
    float* sWl = sm;
    float* sWr = sm + 2048;
    float* sX  = sm + 4096;
    for (int i = threadIdx.x; i < 2048; i += blockDim.x) {
        int j = i >> 6, k = i & 63;
        int idx = (k >> 1) * 64 + (j << 1) + (k & 1);
        sWl[idx] = Wl[i];
        sWr[idx] = Wr[i];
    }
    __syncthreads();
    const unsigned long long* sWl2 = (const unsigned long long*)sWl;
    const unsigned long long* sWr2 = (const unsigned long long*)sWr;
    int warp = threadIdx.x >> 5, lane = threadIdx.x & 31;
    float bj = bl[lane];
    float* sXw = sX + warp * (NT * 64);
    int gwarp = blockIdx.x * 8 + warp;
    int nwarp = gridDim.x * 8;
    __half2* tout2 = (__half2*)tout;
    __half2* sout2 = (__half2*)sout;
    for (int g = gwarp; g < NN / NT; g += nwarp) {
        int v0 = g * NT;
#pragma unroll
        for (int n = 0; n < NT; n++) {
            float2 hv = *(const float2*)(h + (size_t)(v0 + n) * 64 + lane * 2);
            *(float2*)(sXw + n * 64 + lane * 2) = hv;
        }
        __syncwarp();
        unsigned long long at[NT], as[NT];
#pragma unroll
        for (int n = 0; n < NT; n++) {
            at[n] = pk2(0.f, 0.f);
            as[n] = pk2(0.f, 0.f);
        }
        for (int p = 0; p < 32; p += 2) {
            unsigned long long wl0 = sWl2[(p + 0) * 32 + lane];
            unsigned long long wl1 = sWl2[(p + 1) * 32 + lane];
            unsigned long long wr0 = sWr2[(p + 0) * 32 + lane];
            unsigned long long wr1 = sWr2[(p + 1) * 32 + lane];
#pragma unroll
            for (int n = 0; n < NT; n++) {
                float4 a = *(const float4*)(sXw + n * 64 + p * 2);
                unsigned long long a01 = pk2(a.x, a.y);
                unsigned long long a23 = pk2(a.z, a.w);
                fma2(at[n], wl0, a01);
                fma2(at[n], wl1, a23);
                fma2(as[n], wr0, a01);
                fma2(as[n], wr1, a23);
            }
        }
#pragma unroll
        for (int n = 0; n < NT; n++) {
            float tx, ty, sx, sy;
            upk2(at[n], tx, ty);
            upk2(as[n], sx, sy);
            float tj = tx + ty;
            float sj = sx + sy + bj;
            float thi = __shfl_down_sync(0xffffffffu, tj, 1);
            float shi = __shfl_down_sync(0xffffffffu, sj, 1);
            if (!(lane & 1)) {
                tout2[(size_t)(v0 + n) * 16 + (lane >> 1)] = __floats2half2_rn(tj, thi);
                sout2[(size_t)(v0 + n) * 16 + (lane >> 1)] = __floats2half2_rn(sj, shi);
            }
        }
        __syncwarp();
    }
}

// ---------------- k_aggnorm: s fp16 ----------------
__global__ __launch_bounds__(256, 8) void k_aggnorm(const __half* __restrict__ t,
                                                    const __half* __restrict__ s,
                                                    float* __restrict__ out) {
    const __half2* t2 = (const __half2*)t;
    const __half2* s2 = (const __half2*)s;
    int warp = threadIdx.x >> 5, lane = threadIdx.x & 31;
    int m = lane & 15;
    int hi = lane >> 4;
    int gw = blockIdx.x * 8 + warp;
    int nw = gridDim.x * 8;
    for (int v = gw; v < NN; v += nw) {
        int beg = g_off[v], end = g_off[v + 1];
        float ax = 0.f, ay = 0.f;
        for (int base = beg; base < end; base += 32) {
            int rem = end - base;
            int mm = rem < 32 ? rem : 32;
            int sv = (lane < mm) ? g_csr[base + lane] : 0;
            int q = 0;
            for (; q + 8 <= mm; q += 8) {
                int u[4];
#pragma unroll
                for (int i = 0; i < 4; i++)
                    u[i] = __shfl_sync(0xffffffffu, sv, q + 2 * i + hi);
                __half2 hv[4];
#pragma unroll
                for (int i = 0; i < 4; i++) hv[i] = t2[(size_t)u[i] * 16 + m];
#pragma unroll
                for (int i = 0; i < 4; i++) {
                    float2 f = __half22float2(hv[i]);
                    ax += f.x;
                    ay += f.y;
                }
            }
            for (; q + 2 <= mm; q += 2) {
                int u = __shfl_sync(0xffffffffu, sv, q + hi);
                float2 f = __half22float2(t2[(size_t)u * 16 + m]);
                ax += f.x;
                ay += f.y;
            }
            if (q < mm) {
                int u = __shfl_sync(0xffffffffu, sv, q);
                if (!hi) {
                    float2 f = __half22float2(t2[(size_t)u * 16 + m]);
                    ax += f.x;
                    ay += f.y;
                }
            }
        }
        ax += __shfl_xor_sync(0xffffffffu, ax, 16);
        ay += __shfl_xor_sync(0xffffffffu, ay, 16);
        float idg = g_inv[v];
        float2 sv2 = __half22float2(s2[(size_t)v * 16 + m]);
        float ox = ax * idg + sv2.x;
        float oy = ay * idg + sv2.y;
        float ss = ox * ox + oy * oy;
#pragma unroll
        for (int off = 8; off; off >>= 1)
            ss += __shfl_xor_sync(0xffffffffu, ss, off);
        float nrm = fmaxf(sqrtf(ss), 1e-12f);
        if (!hi)
            *(float2*)(out + (size_t)v * 32 + m * 2) = make_float2(ox / nrm, oy / nrm);
    }
}

// ---------------- launch ----------------
extern "C" void kernel_launch(void* const* d_in, const int* in_sizes, int n_in,
                              void* d_out, int out_size) {
    const float* x     = (const float*)d_in[0];
    const int*   ei    = (const int*)d_in[1];
    const float* W_pre = (const float*)d_in[2];
    const float* b_pre = (const float*)d_in[3];
    const float* Wl1 = (const float*)d_in[4];
    const float* bl1 = (const float*)d_in[5];
    const float* Wr1 = (const float*)d_in[6];
    const float* Wl2 = (const float*)d_in[7];
    const float* bl2 = (const float*)d_in[8];
    const float* Wr2 = (const float*)d_in[9];
    const float* Wl3 = (const float*)d_in[10];
    const float* bl3 = (const float*)d_in[11];
    const float* Wr3 = (const float*)d_in[12];
    float* out = (float*)d_out;
    const int* src = ei;
    const int* dst = ei + NE;

    float *ph0, *ph1;
    __half *pt, *ps;
    cudaGetSymbolAddress((void**)&ph0, g_h0);
    cudaGetSymbolAddress((void**)&ph1, g_h1);
    cudaGetSymbolAddress((void**)&pt, g_t);
    cudaGetSymbolAddress((void**)&ps, g_s);

    const int GRIDA = 1184;
    const int GRIDW = 592;
    const int PSMEM = 83200;
    const int TSMEM = 50432;

    cudaFuncSetAttribute(k_wpre, cudaFuncAttributeMaxDynamicSharedMemorySize, PSMEM);
    cudaFuncSetAttribute(k_wtrans, cudaFuncAttributeMaxDynamicSharedMemorySize, TSMEM);

    // Fork: CSR build on a side stream, overlapped with k_wpre + k_wtrans(layer1).
    cudaStream_t s2;
    cudaStreamCreateWithFlags(&s2, cudaStreamNonBlocking);
    cudaEvent_t eFork, eJoin;
    cudaEventCreateWithFlags(&eFork, cudaEventDisableTiming);
    cudaEventCreateWithFlags(&eJoin, cudaEventDisableTiming);

    cudaEventRecord(eFork, 0);
    cudaStreamWaitEvent(s2, eFork, 0);
    k_count<<<(NE / 4 + 255) / 256, 256, 0, s2>>>(dst);
    k_chunksum<<<NCH, 256, 0, s2>>>();
    k_offsets<<<NCH, 256, 0, s2>>>();
    k_fill<<<(NE / 4 + 255) / 256, 256, 0, s2>>>(src, dst);
    cudaEventRecord(eJoin, s2);

    k_wpre<<<296, 256, PSMEM>>>(x, W_pre, b_pre, ph0);
    k_wtrans<<<GRIDW, 256, TSMEM>>>(ph0, Wl1, bl1, Wr1, pt, ps);
    cudaStreamWaitEvent(0, eJoin, 0);

    k_aggrelu<<<GRIDA, 256>>>(pt, ps, ph1);
    k_wtrans<<<GRIDW, 256, TSMEM>>>(ph1, Wl2, bl2, Wr2, pt, ps);
    k_aggrelu<<<GRIDA, 256>>>(pt, ps, ph0);
    k_trans3<<<GRIDW, 256, 32768>>>(ph0, Wl3, bl3, Wr3, pt, ps);
    k_aggnorm<<<GRIDA, 256>>>(pt, ps, out);
}